// round 1
// baseline (speedup 1.0000x reference)
#include <cuda_runtime.h>
#include <cuda_bf16.h>
#include <cstdint>
#include <cmath>

#define BATCH 32768
#define HDIM  512
#define NL    5

// ---------------- static device buffers (no allocation allowed) ----------------
// packed weights, layout per GEMM: [N][3K] bf16, rows = output col n, cols = logical k
#define S2E_SZ (512*1536)      // K=512  -> 3K=1536
#define TF_SZ  (512*3072)      // K=1024 -> 3K=3072
#define S2E_OFF 0
#define TF_OFF  (S2E_OFF + 5*S2E_SZ)
#define FG_OFF  (TF_OFF  + 5*TF_SZ)
#define FW_OFF  (FG_OFF  + 5*S2E_SZ)
#define WG_OFF  (FW_OFF  + 5*TF_SZ)
#define H1_OFF  (WG_OFF  + 5*S2E_SZ)
#define WP_TOTAL (H1_OFF + 4*S2E_SZ)

__device__ __nv_bfloat16 g_WP[WP_TOTAL];
// activation mega buffer per row: [sh_h(512) e_h f_h w_h | sh_l e_l f_l w_l] -> 4096 bf16
__device__ __nv_bfloat16 g_MEGA[(size_t)BATCH * 4096];
// scratch for fm / wm: per row [h(512) | l(512)]
__device__ __nv_bfloat16 g_SCRATCH[(size_t)BATCH * 1024];
// head hiddens: [4][BATCH][h(512)|l(512)]
__device__ __nv_bfloat16 g_HEADH[(size_t)4 * BATCH * 1024];

// ---------------- helpers ----------------
__device__ __forceinline__ void cp16(__nv_bfloat16* s, const __nv_bfloat16* g) {
    uint32_t sa = (uint32_t)__cvta_generic_to_shared(s);
    asm volatile("cp.async.cg.shared.global [%0], [%1], 16;" :: "r"(sa), "l"(g));
}
__device__ __forceinline__ void cp_commit() { asm volatile("cp.async.commit_group;"); }
__device__ __forceinline__ void cp_wait0()  { asm volatile("cp.async.wait_group 0;"); }

// ---------------- setup kernels ----------------
__global__ void split_inputs_kernel(const float* __restrict__ sh, const float* __restrict__ e,
                                    const float* __restrict__ f,  const float* __restrict__ w) {
    int idx = blockIdx.x * 256 + threadIdx.x;
    if (idx >= BATCH * HDIM) return;
    int row = idx >> 9, k = idx & 511;
    __nv_bfloat16* m = g_MEGA + (size_t)row * 4096;
    float v; __nv_bfloat16 h;
    v = sh[idx]; h = __float2bfloat16(v); m[k]        = h; m[2048 + k] = __float2bfloat16(v - __bfloat162float(h));
    v = e[idx];  h = __float2bfloat16(v); m[512 + k]  = h; m[2560 + k] = __float2bfloat16(v - __bfloat162float(h));
    v = f[idx];  h = __float2bfloat16(v); m[1024 + k] = h; m[3072 + k] = __float2bfloat16(v - __bfloat162float(h));
    v = w[idx];  h = __float2bfloat16(v); m[1536 + k] = h; m[3584 + k] = __float2bfloat16(v - __bfloat162float(h));
}

// pack fp32 weight W[K][N] (row-major) -> bf16 Wp[N][3K]: cols [0,K)=hi, [K,2K)=hi, [2K,3K)=lo
__global__ void pack_w_kernel(const float* __restrict__ W, __nv_bfloat16* __restrict__ out,
                              int K, int N) {
    int idx = blockIdx.x * 256 + threadIdx.x;
    int K3 = 3 * K;
    if (idx >= N * K3) return;
    int n = idx / K3;
    int kk = idx - n * K3;
    int seg = (kk >= 2 * K) ? 2 : ((kk >= K) ? 1 : 0);
    int k = kk - seg * K;
    float v = W[(size_t)k * N + n];
    __nv_bfloat16 h = __float2bfloat16(v);
    out[idx] = (seg < 2) ? h : __float2bfloat16(v - __bfloat162float(h));
}

// ---------------- fused split-bf16 GEMM ----------------
// C[B x 512] = A(fp32 via hi/lo bf16 split) @ W(fp32 via 3-term split) + bias, then epilogue.
// A segments along logical 3K: seg0->hi, seg1->lo, seg2->hi (pairs with Wp's [Bh;Bh;Bl]).
#define MODE_PLAIN 0
#define MODE_ADD   1
#define MODE_GATE  2
#define MODE_GELU  3

template<int MODE>
__device__ __forceinline__ void epi_store(int r, int c, float v0, float v1,
    const float* __restrict__ bias,
    __nv_bfloat16* __restrict__ out, int ldo, int o_hi, int o_lo,
    const __nv_bfloat16* __restrict__ aux, int ldx, int x_hi, int x_lo)
{
    v0 += bias[c];
    v1 += bias[c + 1];
    __nv_bfloat16* orow = out + (size_t)r * ldo;
    if (MODE == MODE_ADD || MODE == MODE_GATE) {
        __nv_bfloat162 oh = *(const __nv_bfloat162*)(orow + o_hi + c);
        __nv_bfloat162 ol = *(const __nv_bfloat162*)(orow + o_lo + c);
        float old0 = __bfloat162float(oh.x) + __bfloat162float(ol.x);
        float old1 = __bfloat162float(oh.y) + __bfloat162float(ol.y);
        if (MODE == MODE_ADD) {
            v0 += old0; v1 += old1;
        } else {
            const __nv_bfloat16* xrow = aux + (size_t)r * ldx;
            __nv_bfloat162 xh = *(const __nv_bfloat162*)(xrow + x_hi + c);
            __nv_bfloat162 xl = *(const __nv_bfloat162*)(xrow + x_lo + c);
            float m0 = __bfloat162float(xh.x) + __bfloat162float(xl.x);
            float m1 = __bfloat162float(xh.y) + __bfloat162float(xl.y);
            float g0 = 1.f / (1.f + expf(-v0));
            float g1 = 1.f / (1.f + expf(-v1));
            v0 = old0 + (m0 - old0) * g0;
            v1 = old1 + (m1 - old1) * g1;
        }
    }
    if (MODE == MODE_GELU) {
        v0 = 0.5f * v0 * (1.f + erff(v0 * 0.70710678118654752f));
        v1 = 0.5f * v1 * (1.f + erff(v1 * 0.70710678118654752f));
    }
    __nv_bfloat16 h0 = __float2bfloat16(v0), h1 = __float2bfloat16(v1);
    __nv_bfloat162 hh; hh.x = h0; hh.y = h1;
    __nv_bfloat162 ll;
    ll.x = __float2bfloat16(v0 - __bfloat162float(h0));
    ll.y = __float2bfloat16(v1 - __bfloat162float(h1));
    *(__nv_bfloat162*)(orow + o_hi + c) = hh;
    *(__nv_bfloat162*)(orow + o_lo + c) = ll;
}

template<int MODE>
__global__ void __launch_bounds__(256) gemm_bf16x3(
    const __nv_bfloat16* __restrict__ A, int lda, int a_hi, int a_lo, int K,
    const __nv_bfloat16* __restrict__ Wp,
    const float* __restrict__ bias,
    __nv_bfloat16* __restrict__ out, int ldo, int o_hi, int o_lo,
    const __nv_bfloat16* __restrict__ aux, int ldx, int x_hi, int x_lo)
{
    __shared__ __align__(16) __nv_bfloat16 As[2][128][40];
    __shared__ __align__(16) __nv_bfloat16 Bs[2][128][40];

    const int tid  = threadIdx.x;
    const int lane = tid & 31;
    const int warp = tid >> 5;
    const int wm   = warp >> 1;   // 0..3
    const int wn   = warp & 1;    // 0..1
    const int bm   = blockIdx.x;
    const int bn   = blockIdx.y;
    const int K3   = 3 * K;
    const int KT   = K3 >> 5;

    const int lr = tid >> 2;            // 0..63
    const int lc = (tid & 3) << 3;      // 0,8,16,24

    const __nv_bfloat16* a_base = A  + (size_t)(bm * 128 + lr) * lda + lc;
    const __nv_bfloat16* b_base = Wp + (size_t)(bn * 128 + lr) * K3  + lc;

    float acc[2][8][4];
    #pragma unroll
    for (int i = 0; i < 2; i++)
        #pragma unroll
        for (int j = 0; j < 8; j++)
            #pragma unroll
            for (int q = 0; q < 4; q++) acc[i][j][q] = 0.f;

    auto load_stage = [&](int s, int kt) {
        int k0 = kt << 5;
        int seg = (k0 >= 2 * K) ? 2 : ((k0 >= K) ? 1 : 0);
        int inseg = k0 - seg * K;
        int acol = ((seg == 1) ? a_lo : a_hi) + inseg;
        cp16(&As[s][lr][lc],      a_base + acol);
        cp16(&As[s][lr + 64][lc], a_base + (size_t)64 * lda + acol);
        cp16(&Bs[s][lr][lc],      b_base + k0);
        cp16(&Bs[s][lr + 64][lc], b_base + (size_t)64 * K3 + k0);
        cp_commit();
    };

    load_stage(0, 0);

    for (int kt = 0; kt < KT; kt++) {
        cp_wait0();
        __syncthreads();
        if (kt + 1 < KT) load_stage((kt + 1) & 1, kt + 1);
        const int s = kt & 1;
        #pragma unroll
        for (int kq = 0; kq < 2; kq++) {
            const int kb = kq * 16 + (lane & 3) * 2;
            uint32_t af[2][4], bfr[8][2];
            #pragma unroll
            for (int mi = 0; mi < 2; mi++) {
                const int m0 = wm * 32 + mi * 16 + (lane >> 2);
                af[mi][0] = *(const uint32_t*)&As[s][m0][kb];
                af[mi][1] = *(const uint32_t*)&As[s][m0 + 8][kb];
                af[mi][2] = *(const uint32_t*)&As[s][m0][kb + 8];
                af[mi][3] = *(const uint32_t*)&As[s][m0 + 8][kb + 8];
            }
            #pragma unroll
            for (int ni = 0; ni < 8; ni++) {
                const int n0 = wn * 64 + ni * 8 + (lane >> 2);
                bfr[ni][0] = *(const uint32_t*)&Bs[s][n0][kb];
                bfr[ni][1] = *(const uint32_t*)&Bs[s][n0][kb + 8];
            }
            #pragma unroll
            for (int mi = 0; mi < 2; mi++)
                #pragma unroll
                for (int ni = 0; ni < 8; ni++)
                    asm volatile(
                        "mma.sync.aligned.m16n8k16.row.col.f32.bf16.bf16.f32 "
                        "{%0,%1,%2,%3},{%4,%5,%6,%7},{%8,%9},{%0,%1,%2,%3};"
                        : "+f"(acc[mi][ni][0]), "+f"(acc[mi][ni][1]),
                          "+f"(acc[mi][ni][2]), "+f"(acc[mi][ni][3])
                        : "r"(af[mi][0]), "r"(af[mi][1]), "r"(af[mi][2]), "r"(af[mi][3]),
                          "r"(bfr[ni][0]), "r"(bfr[ni][1]));
        }
        __syncthreads();
    }

    // epilogue
    #pragma unroll
    for (int mi = 0; mi < 2; mi++) {
        #pragma unroll
        for (int ni = 0; ni < 8; ni++) {
            const int r0 = bm * 128 + wm * 32 + mi * 16 + (lane >> 2);
            const int c  = bn * 128 + wn * 64 + ni * 8 + (lane & 3) * 2;
            epi_store<MODE>(r0,     c, acc[mi][ni][0], acc[mi][ni][1], bias, out, ldo, o_hi, o_lo, aux, ldx, x_hi, x_lo);
            epi_store<MODE>(r0 + 8, c, acc[mi][ni][2], acc[mi][ni][3], bias, out, ldo, o_hi, o_lo, aux, ldx, x_hi, x_lo);
        }
    }
}

// ---------------- final tiny projections: out[B,7] ----------------
__global__ void head2_kernel(
    const float* __restrict__ hsW2, const float* __restrict__ hsb2,
    const float* __restrict__ heW2, const float* __restrict__ heb2,
    const float* __restrict__ hfW2, const float* __restrict__ hfb2,
    const float* __restrict__ hwW2, const float* __restrict__ hwb2,
    float* __restrict__ out)
{
    int row  = blockIdx.x * 8 + (threadIdx.x >> 5);
    int lane = threadIdx.x & 31;
    const __nv_bfloat16* h0 = g_HEADH + (size_t)row * 1024;
    const __nv_bfloat16* h1 = g_HEADH + (size_t)(BATCH + row) * 1024;
    const __nv_bfloat16* h2 = g_HEADH + (size_t)(2 * BATCH + row) * 1024;
    const __nv_bfloat16* h3 = g_HEADH + (size_t)(3 * BATCH + row) * 1024;
    float acc[7] = {0.f, 0.f, 0.f, 0.f, 0.f, 0.f, 0.f};
    for (int k = lane; k < 512; k += 32) {
        float x0 = __bfloat162float(h0[k]) + __bfloat162float(h0[512 + k]);
        float x1 = __bfloat162float(h1[k]) + __bfloat162float(h1[512 + k]);
        float x2 = __bfloat162float(h2[k]) + __bfloat162float(h2[512 + k]);
        float x3 = __bfloat162float(h3[k]) + __bfloat162float(h3[512 + k]);
        acc[0] = fmaf(x0, hsW2[k * 3 + 0], acc[0]);
        acc[1] = fmaf(x0, hsW2[k * 3 + 1], acc[1]);
        acc[2] = fmaf(x0, hsW2[k * 3 + 2], acc[2]);
        acc[3] = fmaf(x1, heW2[k],         acc[3]);
        acc[4] = fmaf(x2, hfW2[k],         acc[4]);
        acc[5] = fmaf(x3, hwW2[k * 2 + 0], acc[5]);
        acc[6] = fmaf(x3, hwW2[k * 2 + 1], acc[6]);
    }
    #pragma unroll
    for (int j = 0; j < 7; j++)
        #pragma unroll
        for (int o = 16; o > 0; o >>= 1)
            acc[j] += __shfl_xor_sync(0xffffffffu, acc[j], o);
    if (lane == 0) {
        float* orow = out + (size_t)row * 7;
        orow[0] = acc[0] + hsb2[0];
        orow[1] = acc[1] + hsb2[1];
        orow[2] = acc[2] + hsb2[2];
        orow[3] = acc[3] + heb2[0];
        orow[4] = acc[4] + hfb2[0];
        orow[5] = acc[5] + hwb2[0];
        orow[6] = acc[6] + hwb2[1];
    }
}

// ---------------- host launch ----------------
extern "C" void kernel_launch(void* const* d_in, const int* in_sizes, int n_in,
                              void* d_out, int out_size) {
    (void)in_sizes; (void)n_in; (void)out_size;
    const float* sh    = (const float*)d_in[0];
    const float* el    = (const float*)d_in[1];
    const float* fa    = (const float*)d_in[2];
    const float* wr    = (const float*)d_in[3];
    const float* s2e_W = (const float*)d_in[4];
    const float* s2e_b = (const float*)d_in[5];
    const float* tf_W  = (const float*)d_in[6];
    const float* tf_b  = (const float*)d_in[7];
    const float* fw_W  = (const float*)d_in[8];
    const float* fw_b  = (const float*)d_in[9];
    const float* fg_W  = (const float*)d_in[10];
    const float* fg_b  = (const float*)d_in[11];
    const float* wg_W  = (const float*)d_in[12];
    const float* wg_b  = (const float*)d_in[13];
    const float* hsW1  = (const float*)d_in[14];
    const float* hsb1  = (const float*)d_in[15];
    const float* hsW2  = (const float*)d_in[16];
    const float* hsb2  = (const float*)d_in[17];
    const float* heW1  = (const float*)d_in[18];
    const float* heb1  = (const float*)d_in[19];
    const float* heW2  = (const float*)d_in[20];
    const float* heb2  = (const float*)d_in[21];
    const float* hfW1  = (const float*)d_in[22];
    const float* hfb1  = (const float*)d_in[23];
    const float* hfW2  = (const float*)d_in[24];
    const float* hfb2  = (const float*)d_in[25];
    const float* hwW1  = (const float*)d_in[26];
    const float* hwb1  = (const float*)d_in[27];
    const float* hwW2  = (const float*)d_in[28];
    const float* hwb2  = (const float*)d_in[29];

    __nv_bfloat16 *WP, *MEGA, *SCRATCH, *HEADH;
    cudaGetSymbolAddress((void**)&WP,      g_WP);
    cudaGetSymbolAddress((void**)&MEGA,    g_MEGA);
    cudaGetSymbolAddress((void**)&SCRATCH, g_SCRATCH);
    cudaGetSymbolAddress((void**)&HEADH,   g_HEADH);

    // split the four input activations into hi/lo bf16 in the mega buffer
    split_inputs_kernel<<<(BATCH * HDIM + 255) / 256, 256>>>(sh, el, fa, wr);

    // pack all GEMM weights (transpose + 3-term split)
    auto pack = [&](const float* W, __nv_bfloat16* dst, int K) {
        int total = 512 * 3 * K;
        pack_w_kernel<<<(total + 255) / 256, 256>>>(W, dst, K, 512);
    };
    for (int i = 0; i < NL; i++) {
        pack(s2e_W + (size_t)i * 512 * 512,  WP + S2E_OFF + (size_t)i * S2E_SZ, 512);
        pack(tf_W  + (size_t)i * 1024 * 512, WP + TF_OFF  + (size_t)i * TF_SZ,  1024);
        pack(fg_W  + (size_t)i * 512 * 512,  WP + FG_OFF  + (size_t)i * S2E_SZ, 512);
        pack(fw_W  + (size_t)i * 1024 * 512, WP + FW_OFF  + (size_t)i * TF_SZ,  1024);
        pack(wg_W  + (size_t)i * 512 * 512,  WP + WG_OFF  + (size_t)i * S2E_SZ, 512);
    }
    pack(hsW1, WP + H1_OFF + 0 * S2E_SZ, 512);
    pack(heW1, WP + H1_OFF + 1 * S2E_SZ, 512);
    pack(hfW1, WP + H1_OFF + 2 * S2E_SZ, 512);
    pack(hwW1, WP + H1_OFF + 3 * S2E_SZ, 512);

    dim3 grid(BATCH / 128, 512 / 128);
    for (int i = 0; i < NL; i++) {
        // e = e + sh @ s2e_W + s2e_b    (A = sh; out = e in mega, adds old e)
        gemm_bf16x3<MODE_ADD><<<grid, 256>>>(
            MEGA, 4096, 0, 2048, 512,
            WP + S2E_OFF + (size_t)i * S2E_SZ, s2e_b + i * 512,
            MEGA, 4096, 512, 2560, nullptr, 0, 0, 0);
        // fm = [sh, e] @ tf_W + tf_b
        gemm_bf16x3<MODE_PLAIN><<<grid, 256>>>(
            MEGA, 4096, 0, 2048, 1024,
            WP + TF_OFF + (size_t)i * TF_SZ, tf_b + i * 512,
            SCRATCH, 1024, 0, 512, nullptr, 0, 0, 0);
        // g = sigmoid(fm @ fg_W + fg_b); f = f*(1-g) + fm*g
        gemm_bf16x3<MODE_GATE><<<grid, 256>>>(
            SCRATCH, 1024, 0, 512, 512,
            WP + FG_OFF + (size_t)i * S2E_SZ, fg_b + i * 512,
            MEGA, 4096, 1024, 3072, SCRATCH, 1024, 0, 512);
        // wm = [e, f] @ fw_W + fw_b
        gemm_bf16x3<MODE_PLAIN><<<grid, 256>>>(
            MEGA, 4096, 512, 2560, 1024,
            WP + FW_OFF + (size_t)i * TF_SZ, fw_b + i * 512,
            SCRATCH, 1024, 0, 512, nullptr, 0, 0, 0);
        // g = sigmoid(wm @ wg_W + wg_b); w = w*(1-g) + wm*g
        gemm_bf16x3<MODE_GATE><<<grid, 256>>>(
            SCRATCH, 1024, 0, 512, 512,
            WP + WG_OFF + (size_t)i * S2E_SZ, wg_b + i * 512,
            MEGA, 4096, 1536, 3584, SCRATCH, 1024, 0, 512);
    }

    // heads: hidden = gelu(x @ W1 + b1)
    const int xoff_hi[4] = {0, 512, 1024, 1536};
    const int xoff_lo[4] = {2048, 2560, 3072, 3584};
    const float* hb1[4]  = {hsb1, heb1, hfb1, hwb1};
    for (int j = 0; j < 4; j++) {
        gemm_bf16x3<MODE_GELU><<<grid, 256>>>(
            MEGA, 4096, xoff_hi[j], xoff_lo[j], 512,
            WP + H1_OFF + (size_t)j * S2E_SZ, hb1[j],
            HEADH + (size_t)j * BATCH * 1024, 1024, 0, 512, nullptr, 0, 0, 0);
    }

    // final tiny projections -> [B, 7]
    head2_kernel<<<BATCH / 8, 256>>>(hsW2, hsb2, heW2, heb2, hfW2, hfb2,
                                     hwW2, hwb2, (float*)d_out);
}

// round 3
// speedup vs baseline: 1.4637x; 1.4637x over previous
#include <cuda_runtime.h>
#include <cuda_bf16.h>
#include <cstdint>
#include <cmath>

#define BATCH 32768
#define HDIM  512
#define NL    5

// ---------------- static device buffers ----------------
#define S2E_SZ (512*1536)
#define TF_SZ  (512*3072)
#define S2E_OFF 0
#define TF_OFF  (S2E_OFF + 5*S2E_SZ)
#define FG_OFF  (TF_OFF  + 5*TF_SZ)
#define FW_OFF  (FG_OFF  + 5*S2E_SZ)
#define WG_OFF  (FW_OFF  + 5*TF_SZ)
#define H1_OFF  (WG_OFF  + 5*S2E_SZ)
#define WP_TOTAL (H1_OFF + 4*S2E_SZ)

__device__ __nv_bfloat16 g_WP[WP_TOTAL];
__device__ __nv_bfloat16 g_MEGA[(size_t)BATCH * 4096];
__device__ __nv_bfloat16 g_SCRATCH[(size_t)BATCH * 1024];
__device__ __nv_bfloat16 g_HEADH[(size_t)4 * BATCH * 1024];

// ---------------- helpers ----------------
__device__ __forceinline__ void cp16s(uint32_t sa, const void* g) {
    asm volatile("cp.async.cg.shared.global [%0], [%1], 16;" :: "r"(sa), "l"(g));
}
__device__ __forceinline__ void ldmx4(uint32_t addr, uint32_t& r0, uint32_t& r1, uint32_t& r2, uint32_t& r3) {
    asm volatile("ldmatrix.sync.aligned.m8n8.x4.shared.b16 {%0,%1,%2,%3}, [%4];"
        : "=r"(r0), "=r"(r1), "=r"(r2), "=r"(r3) : "r"(addr));
}

// ---------------- setup kernels ----------------
__global__ void split_inputs_kernel(const float* __restrict__ sh, const float* __restrict__ e,
                                    const float* __restrict__ f,  const float* __restrict__ w) {
    int idx = blockIdx.x * 256 + threadIdx.x;
    if (idx >= BATCH * HDIM) return;
    int row = idx >> 9, k = idx & 511;
    __nv_bfloat16* m = g_MEGA + (size_t)row * 4096;
    float v; __nv_bfloat16 h;
    v = sh[idx]; h = __float2bfloat16(v); m[k]        = h; m[2048 + k] = __float2bfloat16(v - __bfloat162float(h));
    v = e[idx];  h = __float2bfloat16(v); m[512 + k]  = h; m[2560 + k] = __float2bfloat16(v - __bfloat162float(h));
    v = f[idx];  h = __float2bfloat16(v); m[1024 + k] = h; m[3072 + k] = __float2bfloat16(v - __bfloat162float(h));
    v = w[idx];  h = __float2bfloat16(v); m[1536 + k] = h; m[3584 + k] = __float2bfloat16(v - __bfloat162float(h));
}

// tiled transpose pack: fp32 W[L][K][512] -> bf16 out[L][512][3K] ([Bh;Bh;Bl])
__global__ void pack_tiled(const float* __restrict__ W, __nv_bfloat16* __restrict__ out, int K) {
    __shared__ float t[32][33];
    int k0 = blockIdx.x * 32, n0 = blockIdx.y * 32, l = blockIdx.z;
    const float* Wl = W + (size_t)l * K * 512;
    __nv_bfloat16* ol = out + (size_t)l * 512 * 3 * K;
    int r = threadIdx.x >> 5, c = threadIdx.x & 31;
    #pragma unroll
    for (int i = 0; i < 4; i++)
        t[r + 8 * i][c] = Wl[(size_t)(k0 + r + 8 * i) * 512 + n0 + c];
    __syncthreads();
    int K3 = 3 * K;
    #pragma unroll
    for (int i = 0; i < 4; i++) {
        int n = n0 + r + 8 * i;
        float v = t[c][r + 8 * i];
        __nv_bfloat16 h  = __float2bfloat16(v);
        __nv_bfloat16 lo = __float2bfloat16(v - __bfloat162float(h));
        __nv_bfloat16* row = ol + (size_t)n * K3;
        row[k0 + c]         = h;
        row[K + k0 + c]     = h;
        row[2 * K + k0 + c] = lo;
    }
}

// ---------------- ldmatrix + mma.sync GEMM ----------------
#define MODE_PLAIN 0
#define MODE_ADD   1
#define MODE_GATE  2
#define MODE_GELU  3

template<int MODE>
__device__ __forceinline__ void epi_store(int r, int c, float v0, float v1,
    const float* __restrict__ bias,
    __nv_bfloat16* __restrict__ out, int ldo, int o_hi, int o_lo,
    const __nv_bfloat16* __restrict__ aux, int ldx, int x_hi, int x_lo)
{
    v0 += bias[c];
    v1 += bias[c + 1];
    __nv_bfloat16* orow = out + (size_t)r * ldo;
    if (MODE == MODE_ADD || MODE == MODE_GATE) {
        __nv_bfloat162 oh = *(const __nv_bfloat162*)(orow + o_hi + c);
        __nv_bfloat162 ol = *(const __nv_bfloat162*)(orow + o_lo + c);
        float old0 = __bfloat162float(oh.x) + __bfloat162float(ol.x);
        float old1 = __bfloat162float(oh.y) + __bfloat162float(ol.y);
        if (MODE == MODE_ADD) {
            v0 += old0; v1 += old1;
        } else {
            const __nv_bfloat16* xrow = aux + (size_t)r * ldx;
            __nv_bfloat162 xh = *(const __nv_bfloat162*)(xrow + x_hi + c);
            __nv_bfloat162 xl = *(const __nv_bfloat162*)(xrow + x_lo + c);
            float m0 = __bfloat162float(xh.x) + __bfloat162float(xl.x);
            float m1 = __bfloat162float(xh.y) + __bfloat162float(xl.y);
            float g0 = 1.f / (1.f + expf(-v0));
            float g1 = 1.f / (1.f + expf(-v1));
            v0 = old0 + (m0 - old0) * g0;
            v1 = old1 + (m1 - old1) * g1;
        }
    }
    if (MODE == MODE_GELU) {
        v0 = 0.5f * v0 * (1.f + erff(v0 * 0.70710678118654752f));
        v1 = 0.5f * v1 * (1.f + erff(v1 * 0.70710678118654752f));
    }
    __nv_bfloat16 h0 = __float2bfloat16(v0), h1 = __float2bfloat16(v1);
    __nv_bfloat162 hh; hh.x = h0; hh.y = h1;
    __nv_bfloat162 ll;
    ll.x = __float2bfloat16(v0 - __bfloat162float(h0));
    ll.y = __float2bfloat16(v1 - __bfloat162float(h1));
    *(__nv_bfloat162*)(orow + o_hi + c) = hh;
    *(__nv_bfloat162*)(orow + o_lo + c) = ll;
}

// smem: A stage0 [0,16K), A stage1 [16K,32K), B stage0 [32K,48K), B stage1 [48K,64K)
#define SMA(s) ((s) * 16384)
#define SMB(s) (32768 + (s) * 16384)
#define GEMM_SMEM 65536

template<int MODE>
__global__ void __launch_bounds__(256, 2) gemm_lm(
    const __nv_bfloat16* __restrict__ A, int lda, int a_hi, int a_lo, int K,
    const __nv_bfloat16* __restrict__ Wp,
    const float* __restrict__ bias,
    __nv_bfloat16* __restrict__ out, int ldo, int o_hi, int o_lo,
    const __nv_bfloat16* __restrict__ aux, int ldx, int x_hi, int x_lo)
{
    extern __shared__ __align__(1024) char dsm[];
    const uint32_t sb = (uint32_t)__cvta_generic_to_shared(dsm);
    const int tid = threadIdx.x, lane = tid & 31, warp = tid >> 5;
    const int wm = warp >> 1, wn = warp & 1;
    const int bm = blockIdx.x, bn = blockIdx.y;
    const int K3 = 3 * K, KT = K3 >> 6;

    float acc[2][8][4];
    #pragma unroll
    for (int i = 0; i < 2; i++)
        #pragma unroll
        for (int j = 0; j < 8; j++)
            #pragma unroll
            for (int q = 0; q < 4; q++) acc[i][j][q] = 0.f;

    // per-thread load geometry (4 chunks of 16B per array per stage)
    const __nv_bfloat16* Ab = A  + (size_t)bm * 128 * lda;
    const __nv_bfloat16* Bb = Wp + (size_t)bn * 128 * K3;

    auto load_stage = [&](int s, int kt) {
        const int k0 = kt << 6;
        const int seg = (k0 >= 2 * K) ? 2 : ((k0 >= K) ? 1 : 0);
        const int acol = ((seg == 1) ? a_lo : a_hi) + (k0 - seg * K);
        #pragma unroll
        for (int i = 0; i < 4; i++) {
            const int id = tid + 256 * i;
            const int row = id >> 3, c = id & 7;
            const uint32_t sw = (row << 7) | (((c ^ (row & 7)) << 4));
            cp16s(sb + SMA(s) + sw, Ab + (size_t)row * lda + acol + c * 8);
            cp16s(sb + SMB(s) + sw, Bb + (size_t)row * K3  + k0   + c * 8);
        }
        asm volatile("cp.async.commit_group;");
    };

    load_stage(0, 0);

    // ldmatrix lane geometry
    const int lrow = lane & 15;            // row within 16-row tile
    const int lhi  = lane >> 4;            // 0/1 -> k column block
    const int lph  = lane & 7;             // swizzle phase

    const uint32_t aRow0 = (uint32_t)(wm * 32 + lrow) << 7;   // byte row offset
    const uint32_t bRow0 = (uint32_t)(wn * 64 + lrow) << 7;

    for (int kt = 0; kt < KT; kt++) {
        if (kt + 1 < KT) {
            load_stage((kt + 1) & 1, kt + 1);
            asm volatile("cp.async.wait_group 1;");
        } else {
            asm volatile("cp.async.wait_group 0;");
        }
        __syncthreads();
        const int s = kt & 1;
        const uint32_t aS = sb + SMA(s);
        const uint32_t bS = sb + SMB(s);

        #pragma unroll
        for (int kq = 0; kq < 4; kq++) {
            const uint32_t cb = (uint32_t)(((kq * 2 + lhi) ^ lph) << 4);
            uint32_t a[2][4];
            #pragma unroll
            for (int mi = 0; mi < 2; mi++)
                ldmx4(aS + aRow0 + (uint32_t)(mi * 2048) + cb, a[mi][0], a[mi][1], a[mi][2], a[mi][3]);
            uint32_t b[4][4];
            #pragma unroll
            for (int n2 = 0; n2 < 4; n2++)
                ldmx4(bS + bRow0 + (uint32_t)(n2 * 2048) + cb, b[n2][0], b[n2][1], b[n2][2], b[n2][3]);
            #pragma unroll
            for (int mi = 0; mi < 2; mi++)
                #pragma unroll
                for (int ni = 0; ni < 8; ni++)
                    asm volatile(
                        "mma.sync.aligned.m16n8k16.row.col.f32.bf16.bf16.f32 "
                        "{%0,%1,%2,%3},{%4,%5,%6,%7},{%8,%9},{%0,%1,%2,%3};"
                        : "+f"(acc[mi][ni][0]), "+f"(acc[mi][ni][1]),
                          "+f"(acc[mi][ni][2]), "+f"(acc[mi][ni][3])
                        : "r"(a[mi][0]), "r"(a[mi][1]), "r"(a[mi][2]), "r"(a[mi][3]),
                          "r"(b[ni >> 1][ni & 1]), "r"(b[ni >> 1][2 + (ni & 1)]));
        }
        __syncthreads();
    }

    // epilogue straight from accumulators
    #pragma unroll
    for (int mi = 0; mi < 2; mi++) {
        #pragma unroll
        for (int ni = 0; ni < 8; ni++) {
            const int r0 = bm * 128 + wm * 32 + mi * 16 + (lane >> 2);
            const int c  = bn * 128 + wn * 64 + ni * 8 + (lane & 3) * 2;
            epi_store<MODE>(r0,     c, acc[mi][ni][0], acc[mi][ni][1], bias, out, ldo, o_hi, o_lo, aux, ldx, x_hi, x_lo);
            epi_store<MODE>(r0 + 8, c, acc[mi][ni][2], acc[mi][ni][3], bias, out, ldo, o_hi, o_lo, aux, ldx, x_hi, x_lo);
        }
    }
}

// ---------------- final tiny projections ----------------
__global__ void head2_kernel(
    const float* __restrict__ hsW2, const float* __restrict__ hsb2,
    const float* __restrict__ heW2, const float* __restrict__ heb2,
    const float* __restrict__ hfW2, const float* __restrict__ hfb2,
    const float* __restrict__ hwW2, const float* __restrict__ hwb2,
    float* __restrict__ out)
{
    int row  = blockIdx.x * 8 + (threadIdx.x >> 5);
    int lane = threadIdx.x & 31;
    const __nv_bfloat16* h0 = g_HEADH + (size_t)row * 1024;
    const __nv_bfloat16* h1 = g_HEADH + (size_t)(BATCH + row) * 1024;
    const __nv_bfloat16* h2 = g_HEADH + (size_t)(2 * BATCH + row) * 1024;
    const __nv_bfloat16* h3 = g_HEADH + (size_t)(3 * BATCH + row) * 1024;
    float acc[7] = {0.f, 0.f, 0.f, 0.f, 0.f, 0.f, 0.f};
    for (int k = lane; k < 512; k += 32) {
        float x0 = __bfloat162float(h0[k]) + __bfloat162float(h0[512 + k]);
        float x1 = __bfloat162float(h1[k]) + __bfloat162float(h1[512 + k]);
        float x2 = __bfloat162float(h2[k]) + __bfloat162float(h2[512 + k]);
        float x3 = __bfloat162float(h3[k]) + __bfloat162float(h3[512 + k]);
        acc[0] = fmaf(x0, hsW2[k * 3 + 0], acc[0]);
        acc[1] = fmaf(x0, hsW2[k * 3 + 1], acc[1]);
        acc[2] = fmaf(x0, hsW2[k * 3 + 2], acc[2]);
        acc[3] = fmaf(x1, heW2[k],         acc[3]);
        acc[4] = fmaf(x2, hfW2[k],         acc[4]);
        acc[5] = fmaf(x3, hwW2[k * 2 + 0], acc[5]);
        acc[6] = fmaf(x3, hwW2[k * 2 + 1], acc[6]);
    }
    #pragma unroll
    for (int j = 0; j < 7; j++)
        #pragma unroll
        for (int o = 16; o > 0; o >>= 1)
            acc[j] += __shfl_xor_sync(0xffffffffu, acc[j], o);
    if (lane == 0) {
        float* orow = out + (size_t)row * 7;
        orow[0] = acc[0] + hsb2[0];
        orow[1] = acc[1] + hsb2[1];
        orow[2] = acc[2] + hsb2[2];
        orow[3] = acc[3] + heb2[0];
        orow[4] = acc[4] + hfb2[0];
        orow[5] = acc[5] + hwb2[0];
        orow[6] = acc[6] + hwb2[1];
    }
}

// ---------------- host launch ----------------
extern "C" void kernel_launch(void* const* d_in, const int* in_sizes, int n_in,
                              void* d_out, int out_size) {
    (void)in_sizes; (void)n_in; (void)out_size;
    const float* sh    = (const float*)d_in[0];
    const float* el    = (const float*)d_in[1];
    const float* fa    = (const float*)d_in[2];
    const float* wr    = (const float*)d_in[3];
    const float* s2e_W = (const float*)d_in[4];
    const float* s2e_b = (const float*)d_in[5];
    const float* tf_W  = (const float*)d_in[6];
    const float* tf_b  = (const float*)d_in[7];
    const float* fw_W  = (const float*)d_in[8];
    const float* fw_b  = (const float*)d_in[9];
    const float* fg_W  = (const float*)d_in[10];
    const float* fg_b  = (const float*)d_in[11];
    const float* wg_W  = (const float*)d_in[12];
    const float* wg_b  = (const float*)d_in[13];
    const float* hsW1  = (const float*)d_in[14];
    const float* hsb1  = (const float*)d_in[15];
    const float* hsW2  = (const float*)d_in[16];
    const float* hsb2  = (const float*)d_in[17];
    const float* heW1  = (const float*)d_in[18];
    const float* heb1  = (const float*)d_in[19];
    const float* heW2  = (const float*)d_in[20];
    const float* heb2  = (const float*)d_in[21];
    const float* hfW1  = (const float*)d_in[22];
    const float* hfb1  = (const float*)d_in[23];
    const float* hfW2  = (const float*)d_in[24];
    const float* hfb2  = (const float*)d_in[25];
    const float* hwW1  = (const float*)d_in[26];
    const float* hwb1  = (const float*)d_in[27];
    const float* hwW2  = (const float*)d_in[28];
    const float* hwb2  = (const float*)d_in[29];

    __nv_bfloat16 *WP, *MEGA, *SCRATCH, *HEADH;
    cudaGetSymbolAddress((void**)&WP,      g_WP);
    cudaGetSymbolAddress((void**)&MEGA,    g_MEGA);
    cudaGetSymbolAddress((void**)&SCRATCH, g_SCRATCH);
    cudaGetSymbolAddress((void**)&HEADH,   g_HEADH);

    cudaFuncSetAttribute(gemm_lm<MODE_PLAIN>, cudaFuncAttributeMaxDynamicSharedMemorySize, GEMM_SMEM);
    cudaFuncSetAttribute(gemm_lm<MODE_ADD>,   cudaFuncAttributeMaxDynamicSharedMemorySize, GEMM_SMEM);
    cudaFuncSetAttribute(gemm_lm<MODE_GATE>,  cudaFuncAttributeMaxDynamicSharedMemorySize, GEMM_SMEM);
    cudaFuncSetAttribute(gemm_lm<MODE_GELU>,  cudaFuncAttributeMaxDynamicSharedMemorySize, GEMM_SMEM);

    split_inputs_kernel<<<(BATCH * HDIM + 255) / 256, 256>>>(sh, el, fa, wr);

    pack_tiled<<<dim3(16, 16, 5), 256>>>(s2e_W, WP + S2E_OFF, 512);
    pack_tiled<<<dim3(32, 16, 5), 256>>>(tf_W,  WP + TF_OFF,  1024);
    pack_tiled<<<dim3(16, 16, 5), 256>>>(fg_W,  WP + FG_OFF,  512);
    pack_tiled<<<dim3(32, 16, 5), 256>>>(fw_W,  WP + FW_OFF,  1024);
    pack_tiled<<<dim3(16, 16, 5), 256>>>(wg_W,  WP + WG_OFF,  512);
    pack_tiled<<<dim3(16, 16, 1), 256>>>(hsW1, WP + H1_OFF + 0 * S2E_SZ, 512);
    pack_tiled<<<dim3(16, 16, 1), 256>>>(heW1, WP + H1_OFF + 1 * S2E_SZ, 512);
    pack_tiled<<<dim3(16, 16, 1), 256>>>(hfW1, WP + H1_OFF + 2 * S2E_SZ, 512);
    pack_tiled<<<dim3(16, 16, 1), 256>>>(hwW1, WP + H1_OFF + 3 * S2E_SZ, 512);

    dim3 grid(BATCH / 128, 512 / 128);
    for (int i = 0; i < NL; i++) {
        gemm_lm<MODE_ADD><<<grid, 256, GEMM_SMEM>>>(
            MEGA, 4096, 0, 2048, 512,
            WP + S2E_OFF + (size_t)i * S2E_SZ, s2e_b + i * 512,
            MEGA, 4096, 512, 2560, nullptr, 0, 0, 0);
        gemm_lm<MODE_PLAIN><<<grid, 256, GEMM_SMEM>>>(
            MEGA, 4096, 0, 2048, 1024,
            WP + TF_OFF + (size_t)i * TF_SZ, tf_b + i * 512,
            SCRATCH, 1024, 0, 512, nullptr, 0, 0, 0);
        gemm_lm<MODE_GATE><<<grid, 256, GEMM_SMEM>>>(
            SCRATCH, 1024, 0, 512, 512,
            WP + FG_OFF + (size_t)i * S2E_SZ, fg_b + i * 512,
            MEGA, 4096, 1024, 3072, SCRATCH, 1024, 0, 512);
        gemm_lm<MODE_PLAIN><<<grid, 256, GEMM_SMEM>>>(
            MEGA, 4096, 512, 2560, 1024,
            WP + FW_OFF + (size_t)i * TF_SZ, fw_b + i * 512,
            SCRATCH, 1024, 0, 512, nullptr, 0, 0, 0);
        gemm_lm<MODE_GATE><<<grid, 256, GEMM_SMEM>>>(
            SCRATCH, 1024, 0, 512, 512,
            WP + WG_OFF + (size_t)i * S2E_SZ, wg_b + i * 512,
            MEGA, 4096, 1536, 3584, SCRATCH, 1024, 0, 512);
    }

    const int xoff_hi[4] = {0, 512, 1024, 1536};
    const int xoff_lo[4] = {2048, 2560, 3072, 3584};
    const float* hb1[4]  = {hsb1, heb1, hfb1, hwb1};
    for (int j = 0; j < 4; j++) {
        gemm_lm<MODE_GELU><<<grid, 256, GEMM_SMEM>>>(
            MEGA, 4096, xoff_hi[j], xoff_lo[j], 512,
            WP + H1_OFF + (size_t)j * S2E_SZ, hb1[j],
            HEADH + (size_t)j * BATCH * 1024, 1024, 0, 512, nullptr, 0, 0, 0);
    }

    head2_kernel<<<BATCH / 8, 256>>>(hsW2, hsb2, heW2, heb2, hfW2, hfb2,
                                     hwW2, hwb2, (float*)d_out);
}

// round 4
// speedup vs baseline: 1.8578x; 1.2693x over previous
#include <cuda_runtime.h>
#include <cuda_fp16.h>
#include <cstdint>
#include <cmath>

#define BATCH 32768
#define HDIM  512
#define NL    5

// ---------------- static device buffers ----------------
// fp16 weights: [N=512][K], K-major (B rows = output cols)
#define S2E_SZ (512*512)
#define TF_SZ  (512*1024)
#define S2E_OFF 0
#define TF_OFF  (S2E_OFF + 5*S2E_SZ)
#define FG_OFF  (TF_OFF  + 5*TF_SZ)
#define FW_OFF  (FG_OFF  + 5*S2E_SZ)
#define WG_OFF  (FW_OFF  + 5*TF_SZ)
#define H1_OFF  (WG_OFF  + 5*S2E_SZ)
#define WP_TOTAL (H1_OFF + 4*S2E_SZ)

__device__ __half g_WP[WP_TOTAL];
// activation mega buffer per row: [sh_h(512) e_h f_h w_h | sh_l e_l f_l w_l] -> 4096 halves
__device__ __half g_MEGA[(size_t)BATCH * 4096];
__device__ __half g_SCRATCH[(size_t)BATCH * 1024];
__device__ __half g_HEADH[(size_t)4 * BATCH * 1024];

// ---------------- helpers ----------------
__device__ __forceinline__ void cp16s(uint32_t sa, const void* g) {
    asm volatile("cp.async.cg.shared.global [%0], [%1], 16;" :: "r"(sa), "l"(g));
}
__device__ __forceinline__ void ldmx4(uint32_t addr, uint32_t& r0, uint32_t& r1, uint32_t& r2, uint32_t& r3) {
    asm volatile("ldmatrix.sync.aligned.m8n8.x4.shared.b16 {%0,%1,%2,%3}, [%4];"
        : "=r"(r0), "=r"(r1), "=r"(r2), "=r"(r3) : "r"(addr));
}
#define MMA16(acc, a0,a1,a2,a3, b0,b1) \
    asm volatile("mma.sync.aligned.m16n8k16.row.col.f32.f16.f16.f32 " \
        "{%0,%1,%2,%3},{%4,%5,%6,%7},{%8,%9},{%0,%1,%2,%3};" \
        : "+f"((acc)[0]), "+f"((acc)[1]), "+f"((acc)[2]), "+f"((acc)[3]) \
        : "r"(a0), "r"(a1), "r"(a2), "r"(a3), "r"(b0), "r"(b1))

// ---------------- setup kernels ----------------
__global__ void split_inputs_kernel(const float* __restrict__ sh, const float* __restrict__ e,
                                    const float* __restrict__ f,  const float* __restrict__ w) {
    int idx = blockIdx.x * 256 + threadIdx.x;
    if (idx >= BATCH * HDIM) return;
    int row = idx >> 9, k = idx & 511;
    __half* m = g_MEGA + (size_t)row * 4096;
    float v; __half h;
    v = sh[idx]; h = __float2half(v); m[k]        = h; m[2048 + k] = __float2half(v - __half2float(h));
    v = e[idx];  h = __float2half(v); m[512 + k]  = h; m[2560 + k] = __float2half(v - __half2float(h));
    v = f[idx];  h = __float2half(v); m[1024 + k] = h; m[3072 + k] = __float2half(v - __half2float(h));
    v = w[idx];  h = __float2half(v); m[1536 + k] = h; m[3584 + k] = __float2half(v - __half2float(h));
}

// tiled transpose pack: fp32 W[L][K][512] -> fp16 out[L][512][K]
__global__ void pack_tiled(const float* __restrict__ W, __half* __restrict__ out, int K) {
    __shared__ float t[32][33];
    int k0 = blockIdx.x * 32, n0 = blockIdx.y * 32, l = blockIdx.z;
    const float* Wl = W + (size_t)l * K * 512;
    __half* ol = out + (size_t)l * 512 * K;
    int r = threadIdx.x >> 5, c = threadIdx.x & 31;
    #pragma unroll
    for (int i = 0; i < 4; i++)
        t[r + 8 * i][c] = Wl[(size_t)(k0 + r + 8 * i) * 512 + n0 + c];
    __syncthreads();
    #pragma unroll
    for (int i = 0; i < 4; i++) {
        int n = n0 + r + 8 * i;
        ol[(size_t)n * K + k0 + c] = __float2half(t[c][r + 8 * i]);
    }
}

// ---------------- ldmatrix + mma.sync fp16x2 GEMM ----------------
#define MODE_PLAIN 0
#define MODE_ADD   1
#define MODE_GATE  2
#define MODE_GELU  3

template<int MODE>
__device__ __forceinline__ void epi_store(int r, int c, float v0, float v1,
    const float* __restrict__ bias,
    __half* __restrict__ out, int ldo, int o_hi, int o_lo,
    const __half* __restrict__ aux, int ldx, int x_hi, int x_lo)
{
    v0 += bias[c];
    v1 += bias[c + 1];
    __half* orow = out + (size_t)r * ldo;
    if (MODE == MODE_ADD || MODE == MODE_GATE) {
        __half2 oh = *(const __half2*)(orow + o_hi + c);
        __half2 ol = *(const __half2*)(orow + o_lo + c);
        float old0 = __half2float(oh.x) + __half2float(ol.x);
        float old1 = __half2float(oh.y) + __half2float(ol.y);
        if (MODE == MODE_ADD) {
            v0 += old0; v1 += old1;
        } else {
            const __half* xrow = aux + (size_t)r * ldx;
            __half2 xh = *(const __half2*)(xrow + x_hi + c);
            __half2 xl = *(const __half2*)(xrow + x_lo + c);
            float m0 = __half2float(xh.x) + __half2float(xl.x);
            float m1 = __half2float(xh.y) + __half2float(xl.y);
            float g0 = 1.f / (1.f + expf(-v0));
            float g1 = 1.f / (1.f + expf(-v1));
            v0 = old0 + (m0 - old0) * g0;
            v1 = old1 + (m1 - old1) * g1;
        }
    }
    if (MODE == MODE_GELU) {
        v0 = 0.5f * v0 * (1.f + erff(v0 * 0.70710678118654752f));
        v1 = 0.5f * v1 * (1.f + erff(v1 * 0.70710678118654752f));
    }
    __half h0 = __float2half(v0), h1 = __float2half(v1);
    __half2 hh; hh.x = h0; hh.y = h1;
    __half2 ll;
    ll.x = __float2half(v0 - __half2float(h0));
    ll.y = __float2half(v1 - __half2float(h1));
    *(__half2*)(orow + o_hi + c) = hh;
    *(__half2*)(orow + o_lo + c) = ll;
}

// smem per stage: A-hi 16K, A-lo 16K, B 16K -> 48K; two stages = 96K
#define SAH(s) ((s) * 49152)
#define SAL(s) ((s) * 49152 + 16384)
#define SBB(s) ((s) * 49152 + 32768)
#define GEMM_SMEM 98304

template<int MODE>
__global__ void __launch_bounds__(256, 2) gemm_lm(
    const __half* __restrict__ A, int lda, int a_hi, int a_lo, int K,
    const __half* __restrict__ Wp,
    const float* __restrict__ bias,
    __half* __restrict__ out, int ldo, int o_hi, int o_lo,
    const __half* __restrict__ aux, int ldx, int x_hi, int x_lo)
{
    extern __shared__ __align__(1024) char dsm[];
    const uint32_t sb = (uint32_t)__cvta_generic_to_shared(dsm);
    const int tid = threadIdx.x, lane = tid & 31, warp = tid >> 5;
    const int wm = warp >> 1, wn = warp & 1;
    const int bm = blockIdx.x, bn = blockIdx.y;
    const int KT = K >> 6;

    float acc[2][8][4];
    #pragma unroll
    for (int i = 0; i < 2; i++)
        #pragma unroll
        for (int j = 0; j < 8; j++)
            #pragma unroll
            for (int q = 0; q < 4; q++) acc[i][j][q] = 0.f;

    const __half* Ab = A  + (size_t)bm * 128 * lda;
    const __half* Bb = Wp + (size_t)bn * 128 * K;

    auto load_stage = [&](int s, int kt) {
        const int k0 = kt << 6;
        #pragma unroll
        for (int i = 0; i < 4; i++) {
            const int id = tid + 256 * i;
            const int row = id >> 3, c = id & 7;
            const uint32_t sw = (row << 7) | ((c ^ (row & 7)) << 4);
            cp16s(sb + SAH(s) + sw, Ab + (size_t)row * lda + a_hi + k0 + c * 8);
            cp16s(sb + SAL(s) + sw, Ab + (size_t)row * lda + a_lo + k0 + c * 8);
            cp16s(sb + SBB(s) + sw, Bb + (size_t)row * K   + k0   + c * 8);
        }
        asm volatile("cp.async.commit_group;");
    };

    load_stage(0, 0);

    const int lrow = lane & 15;
    const int lhi  = lane >> 4;
    const int lph  = lane & 7;
    const uint32_t aRow0 = (uint32_t)(wm * 32 + lrow) << 7;
    const uint32_t bRow0 = (uint32_t)(wn * 64 + lrow) << 7;

    for (int kt = 0; kt < KT; kt++) {
        if (kt + 1 < KT) {
            load_stage((kt + 1) & 1, kt + 1);
            asm volatile("cp.async.wait_group 1;");
        } else {
            asm volatile("cp.async.wait_group 0;");
        }
        __syncthreads();
        const int s = kt & 1;
        const uint32_t aH = sb + SAH(s);
        const uint32_t aL = sb + SAL(s);
        const uint32_t bS = sb + SBB(s);

        #pragma unroll
        for (int kq = 0; kq < 4; kq++) {
            const uint32_t cb = (uint32_t)(((kq * 2 + lhi) ^ lph) << 4);
            uint32_t ah[2][4], al[2][4], b[4][4];
            #pragma unroll
            for (int mi = 0; mi < 2; mi++) {
                ldmx4(aH + aRow0 + (uint32_t)(mi * 2048) + cb, ah[mi][0], ah[mi][1], ah[mi][2], ah[mi][3]);
                ldmx4(aL + aRow0 + (uint32_t)(mi * 2048) + cb, al[mi][0], al[mi][1], al[mi][2], al[mi][3]);
            }
            #pragma unroll
            for (int n2 = 0; n2 < 4; n2++)
                ldmx4(bS + bRow0 + (uint32_t)(n2 * 2048) + cb, b[n2][0], b[n2][1], b[n2][2], b[n2][3]);
            #pragma unroll
            for (int mi = 0; mi < 2; mi++)
                #pragma unroll
                for (int ni = 0; ni < 8; ni++) {
                    const uint32_t b0 = b[ni >> 1][ni & 1];
                    const uint32_t b1 = b[ni >> 1][2 + (ni & 1)];
                    MMA16(acc[mi][ni], ah[mi][0], ah[mi][1], ah[mi][2], ah[mi][3], b0, b1);
                    MMA16(acc[mi][ni], al[mi][0], al[mi][1], al[mi][2], al[mi][3], b0, b1);
                }
        }
        __syncthreads();
    }

    #pragma unroll
    for (int mi = 0; mi < 2; mi++) {
        #pragma unroll
        for (int ni = 0; ni < 8; ni++) {
            const int r0 = bm * 128 + wm * 32 + mi * 16 + (lane >> 2);
            const int c  = bn * 128 + wn * 64 + ni * 8 + (lane & 3) * 2;
            epi_store<MODE>(r0,     c, acc[mi][ni][0], acc[mi][ni][1], bias, out, ldo, o_hi, o_lo, aux, ldx, x_hi, x_lo);
            epi_store<MODE>(r0 + 8, c, acc[mi][ni][2], acc[mi][ni][3], bias, out, ldo, o_hi, o_lo, aux, ldx, x_hi, x_lo);
        }
    }
}

// ---------------- final tiny projections ----------------
__global__ void head2_kernel(
    const float* __restrict__ hsW2, const float* __restrict__ hsb2,
    const float* __restrict__ heW2, const float* __restrict__ heb2,
    const float* __restrict__ hfW2, const float* __restrict__ hfb2,
    const float* __restrict__ hwW2, const float* __restrict__ hwb2,
    float* __restrict__ out)
{
    int row  = blockIdx.x * 8 + (threadIdx.x >> 5);
    int lane = threadIdx.x & 31;
    const __half* h0 = g_HEADH + (size_t)row * 1024;
    const __half* h1 = g_HEADH + (size_t)(BATCH + row) * 1024;
    const __half* h2 = g_HEADH + (size_t)(2 * BATCH + row) * 1024;
    const __half* h3 = g_HEADH + (size_t)(3 * BATCH + row) * 1024;
    float acc[7] = {0.f, 0.f, 0.f, 0.f, 0.f, 0.f, 0.f};
    for (int k = lane; k < 512; k += 32) {
        float x0 = __half2float(h0[k]) + __half2float(h0[512 + k]);
        float x1 = __half2float(h1[k]) + __half2float(h1[512 + k]);
        float x2 = __half2float(h2[k]) + __half2float(h2[512 + k]);
        float x3 = __half2float(h3[k]) + __half2float(h3[512 + k]);
        acc[0] = fmaf(x0, hsW2[k * 3 + 0], acc[0]);
        acc[1] = fmaf(x0, hsW2[k * 3 + 1], acc[1]);
        acc[2] = fmaf(x0, hsW2[k * 3 + 2], acc[2]);
        acc[3] = fmaf(x1, heW2[k],         acc[3]);
        acc[4] = fmaf(x2, hfW2[k],         acc[4]);
        acc[5] = fmaf(x3, hwW2[k * 2 + 0], acc[5]);
        acc[6] = fmaf(x3, hwW2[k * 2 + 1], acc[6]);
    }
    #pragma unroll
    for (int j = 0; j < 7; j++)
        #pragma unroll
        for (int o = 16; o > 0; o >>= 1)
            acc[j] += __shfl_xor_sync(0xffffffffu, acc[j], o);
    if (lane == 0) {
        float* orow = out + (size_t)row * 7;
        orow[0] = acc[0] + hsb2[0];
        orow[1] = acc[1] + hsb2[1];
        orow[2] = acc[2] + hsb2[2];
        orow[3] = acc[3] + heb2[0];
        orow[4] = acc[4] + hfb2[0];
        orow[5] = acc[5] + hwb2[0];
        orow[6] = acc[6] + hwb2[1];
    }
}

// ---------------- host launch ----------------
extern "C" void kernel_launch(void* const* d_in, const int* in_sizes, int n_in,
                              void* d_out, int out_size) {
    (void)in_sizes; (void)n_in; (void)out_size;
    const float* sh    = (const float*)d_in[0];
    const float* el    = (const float*)d_in[1];
    const float* fa    = (const float*)d_in[2];
    const float* wr    = (const float*)d_in[3];
    const float* s2e_W = (const float*)d_in[4];
    const float* s2e_b = (const float*)d_in[5];
    const float* tf_W  = (const float*)d_in[6];
    const float* tf_b  = (const float*)d_in[7];
    const float* fw_W  = (const float*)d_in[8];
    const float* fw_b  = (const float*)d_in[9];
    const float* fg_W  = (const float*)d_in[10];
    const float* fg_b  = (const float*)d_in[11];
    const float* wg_W  = (const float*)d_in[12];
    const float* wg_b  = (const float*)d_in[13];
    const float* hsW1  = (const float*)d_in[14];
    const float* hsb1  = (const float*)d_in[15];
    const float* hsW2  = (const float*)d_in[16];
    const float* hsb2  = (const float*)d_in[17];
    const float* heW1  = (const float*)d_in[18];
    const float* heb1  = (const float*)d_in[19];
    const float* heW2  = (const float*)d_in[20];
    const float* heb2  = (const float*)d_in[21];
    const float* hfW1  = (const float*)d_in[22];
    const float* hfb1  = (const float*)d_in[23];
    const float* hfW2  = (const float*)d_in[24];
    const float* hfb2  = (const float*)d_in[25];
    const float* hwW1  = (const float*)d_in[26];
    const float* hwb1  = (const float*)d_in[27];
    const float* hwW2  = (const float*)d_in[28];
    const float* hwb2  = (const float*)d_in[29];

    __half *WP, *MEGA, *SCRATCH, *HEADH;
    cudaGetSymbolAddress((void**)&WP,      g_WP);
    cudaGetSymbolAddress((void**)&MEGA,    g_MEGA);
    cudaGetSymbolAddress((void**)&SCRATCH, g_SCRATCH);
    cudaGetSymbolAddress((void**)&HEADH,   g_HEADH);

    cudaFuncSetAttribute(gemm_lm<MODE_PLAIN>, cudaFuncAttributeMaxDynamicSharedMemorySize, GEMM_SMEM);
    cudaFuncSetAttribute(gemm_lm<MODE_ADD>,   cudaFuncAttributeMaxDynamicSharedMemorySize, GEMM_SMEM);
    cudaFuncSetAttribute(gemm_lm<MODE_GATE>,  cudaFuncAttributeMaxDynamicSharedMemorySize, GEMM_SMEM);
    cudaFuncSetAttribute(gemm_lm<MODE_GELU>,  cudaFuncAttributeMaxDynamicSharedMemorySize, GEMM_SMEM);

    split_inputs_kernel<<<(BATCH * HDIM + 255) / 256, 256>>>(sh, el, fa, wr);

    pack_tiled<<<dim3(16, 16, 5), 256>>>(s2e_W, WP + S2E_OFF, 512);
    pack_tiled<<<dim3(32, 16, 5), 256>>>(tf_W,  WP + TF_OFF,  1024);
    pack_tiled<<<dim3(16, 16, 5), 256>>>(fg_W,  WP + FG_OFF,  512);
    pack_tiled<<<dim3(32, 16, 5), 256>>>(fw_W,  WP + FW_OFF,  1024);
    pack_tiled<<<dim3(16, 16, 5), 256>>>(wg_W,  WP + WG_OFF,  512);
    pack_tiled<<<dim3(16, 16, 1), 256>>>(hsW1, WP + H1_OFF + 0 * S2E_SZ, 512);
    pack_tiled<<<dim3(16, 16, 1), 256>>>(heW1, WP + H1_OFF + 1 * S2E_SZ, 512);
    pack_tiled<<<dim3(16, 16, 1), 256>>>(hfW1, WP + H1_OFF + 2 * S2E_SZ, 512);
    pack_tiled<<<dim3(16, 16, 1), 256>>>(hwW1, WP + H1_OFF + 3 * S2E_SZ, 512);

    dim3 grid(BATCH / 128, 512 / 128);
    for (int i = 0; i < NL; i++) {
        gemm_lm<MODE_ADD><<<grid, 256, GEMM_SMEM>>>(
            MEGA, 4096, 0, 2048, 512,
            WP + S2E_OFF + (size_t)i * S2E_SZ, s2e_b + i * 512,
            MEGA, 4096, 512, 2560, nullptr, 0, 0, 0);
        gemm_lm<MODE_PLAIN><<<grid, 256, GEMM_SMEM>>>(
            MEGA, 4096, 0, 2048, 1024,
            WP + TF_OFF + (size_t)i * TF_SZ, tf_b + i * 512,
            SCRATCH, 1024, 0, 512, nullptr, 0, 0, 0);
        gemm_lm<MODE_GATE><<<grid, 256, GEMM_SMEM>>>(
            SCRATCH, 1024, 0, 512, 512,
            WP + FG_OFF + (size_t)i * S2E_SZ, fg_b + i * 512,
            MEGA, 4096, 1024, 3072, SCRATCH, 1024, 0, 512);
        gemm_lm<MODE_PLAIN><<<grid, 256, GEMM_SMEM>>>(
            MEGA, 4096, 512, 2560, 1024,
            WP + FW_OFF + (size_t)i * TF_SZ, fw_b + i * 512,
            SCRATCH, 1024, 0, 512, nullptr, 0, 0, 0);
        gemm_lm<MODE_GATE><<<grid, 256, GEMM_SMEM>>>(
            SCRATCH, 1024, 0, 512, 512,
            WP + WG_OFF + (size_t)i * S2E_SZ, wg_b + i * 512,
            MEGA, 4096, 1536, 3584, SCRATCH, 1024, 0, 512);
    }

    const int xoff_hi[4] = {0, 512, 1024, 1536};
    const int xoff_lo[4] = {2048, 2560, 3072, 3584};
    const float* hb1[4]  = {hsb1, heb1, hfb1, hwb1};
    for (int j = 0; j < 4; j++) {
        gemm_lm<MODE_GELU><<<grid, 256, GEMM_SMEM>>>(
            MEGA, 4096, xoff_hi[j], xoff_lo[j], 512,
            WP + H1_OFF + (size_t)j * S2E_SZ, hb1[j],
            HEADH + (size_t)j * BATCH * 1024, 1024, 0, 512, nullptr, 0, 0, 0);
    }

    head2_kernel<<<BATCH / 8, 256>>>(hsW2, hsb2, heW2, heb2, hfW2, hfb2,
                                     hwW2, hwb2, (float*)d_out);
}

// round 5
// speedup vs baseline: 2.7556x; 1.4832x over previous
#include <cuda_runtime.h>
#include <cuda_fp16.h>
#include <cstdint>
#include <cmath>

#define BATCH 32768
#define HDIM  512
#define NL    5

// ---------------- static device buffers ----------------
// fp16 weights: [N=512][K], K-major (B rows = output cols)
#define S2E_SZ (512*512)
#define TF_SZ  (512*1024)
#define S2E_OFF 0
#define TF_OFF  (S2E_OFF + 5*S2E_SZ)
#define FG_OFF  (TF_OFF  + 5*TF_SZ)
#define FW_OFF  (FG_OFF  + 5*S2E_SZ)
#define WG_OFF  (FW_OFF  + 5*TF_SZ)
#define H1_OFF  (WG_OFF  + 5*S2E_SZ)
#define WP_TOTAL (H1_OFF + 4*S2E_SZ)

__device__ __half g_WP[WP_TOTAL];
// activation mega buffer per row: [sh_h(512) e_h f_h w_h | sh_l e_l f_l w_l] -> 4096 halves
__device__ __half g_MEGA[(size_t)BATCH * 4096];
__device__ __half g_SCRATCH[(size_t)BATCH * 1024];
__device__ __half g_HEADH[(size_t)4 * BATCH * 1024];

// ---------------- helpers ----------------
__device__ __forceinline__ void cp16s(uint32_t sa, const void* g) {
    asm volatile("cp.async.cg.shared.global [%0], [%1], 16;" :: "r"(sa), "l"(g));
}
__device__ __forceinline__ void ldmx4(uint32_t addr, uint32_t& r0, uint32_t& r1, uint32_t& r2, uint32_t& r3) {
    asm volatile("ldmatrix.sync.aligned.m8n8.x4.shared.b16 {%0,%1,%2,%3}, [%4];"
        : "=r"(r0), "=r"(r1), "=r"(r2), "=r"(r3) : "r"(addr));
}
#define MMA16(acc, a0,a1,a2,a3, b0,b1) \
    asm volatile("mma.sync.aligned.m16n8k16.row.col.f32.f16.f16.f32 " \
        "{%0,%1,%2,%3},{%4,%5,%6,%7},{%8,%9},{%0,%1,%2,%3};" \
        : "+f"((acc)[0]), "+f"((acc)[1]), "+f"((acc)[2]), "+f"((acc)[3]) \
        : "r"(a0), "r"(a1), "r"(a2), "r"(a3), "r"(b0), "r"(b1))

// ---------------- setup kernels ----------------
__global__ void split_inputs_kernel(const float* __restrict__ sh, const float* __restrict__ e,
                                    const float* __restrict__ f,  const float* __restrict__ w) {
    int idx = blockIdx.x * 256 + threadIdx.x;
    if (idx >= BATCH * HDIM) return;
    int row = idx >> 9, k = idx & 511;
    __half* m = g_MEGA + (size_t)row * 4096;
    float v; __half h;
    v = sh[idx]; h = __float2half(v); m[k]        = h; m[2048 + k] = __float2half(v - __half2float(h));
    v = e[idx];  h = __float2half(v); m[512 + k]  = h; m[2560 + k] = __float2half(v - __half2float(h));
    v = f[idx];  h = __float2half(v); m[1024 + k] = h; m[3072 + k] = __float2half(v - __half2float(h));
    v = w[idx];  h = __float2half(v); m[1536 + k] = h; m[3584 + k] = __float2half(v - __half2float(h));
}

// tiled transpose pack: fp32 W[L][K][512] -> fp16 out[L][512][K]
__global__ void pack_tiled(const float* __restrict__ W, __half* __restrict__ out, int K) {
    __shared__ float t[32][33];
    int k0 = blockIdx.x * 32, n0 = blockIdx.y * 32, l = blockIdx.z;
    const float* Wl = W + (size_t)l * K * 512;
    __half* ol = out + (size_t)l * 512 * K;
    int r = threadIdx.x >> 5, c = threadIdx.x & 31;
    #pragma unroll
    for (int i = 0; i < 4; i++)
        t[r + 8 * i][c] = Wl[(size_t)(k0 + r + 8 * i) * 512 + n0 + c];
    __syncthreads();
    #pragma unroll
    for (int i = 0; i < 4; i++) {
        int n = n0 + r + 8 * i;
        ol[(size_t)n * K + k0 + c] = __float2half(t[c][r + 8 * i]);
    }
}

// ---------------- ldmatrix + mma.sync fp16 GEMM (single-A, exact hi/lo state) ----------------
#define MODE_PLAIN 0
#define MODE_ADD   1
#define MODE_GATE  2
#define MODE_GELU  3

template<int MODE>
__device__ __forceinline__ void epi_store(int r, int c, float v0, float v1,
    const float* __restrict__ bias,
    __half* __restrict__ out, int ldo, int o_hi, int o_lo,
    const __half* __restrict__ aux, int ldx, int x_hi, int x_lo)
{
    v0 += bias[c];
    v1 += bias[c + 1];
    __half* orow = out + (size_t)r * ldo;
    if (MODE == MODE_ADD || MODE == MODE_GATE) {
        __half2 oh = *(const __half2*)(orow + o_hi + c);
        __half2 ol = *(const __half2*)(orow + o_lo + c);
        float old0 = __half2float(oh.x) + __half2float(ol.x);
        float old1 = __half2float(oh.y) + __half2float(ol.y);
        if (MODE == MODE_ADD) {
            v0 += old0; v1 += old1;
        } else {
            const __half* xrow = aux + (size_t)r * ldx;
            __half2 xh = *(const __half2*)(xrow + x_hi + c);
            __half2 xl = *(const __half2*)(xrow + x_lo + c);
            float m0 = __half2float(xh.x) + __half2float(xl.x);
            float m1 = __half2float(xh.y) + __half2float(xl.y);
            float g0 = 1.f / (1.f + expf(-v0));
            float g1 = 1.f / (1.f + expf(-v1));
            v0 = old0 + (m0 - old0) * g0;
            v1 = old1 + (m1 - old1) * g1;
        }
    }
    if (MODE == MODE_GELU) {
        v0 = 0.5f * v0 * (1.f + erff(v0 * 0.70710678118654752f));
        v1 = 0.5f * v1 * (1.f + erff(v1 * 0.70710678118654752f));
    }
    __half h0 = __float2half(v0), h1 = __float2half(v1);
    __half2 hh; hh.x = h0; hh.y = h1;
    __half2 ll;
    ll.x = __float2half(v0 - __half2float(h0));
    ll.y = __float2half(v1 - __half2float(h1));
    *(__half2*)(orow + o_hi + c) = hh;
    *(__half2*)(orow + o_lo + c) = ll;
}

// smem per stage: A 16K + B 16K = 32K; three stages = 96K
#define SAH(s) ((s) * 32768)
#define SBB(s) ((s) * 32768 + 16384)
#define GEMM_SMEM 98304

template<int MODE>
__global__ void __launch_bounds__(256, 2) gemm_lm(
    const __half* __restrict__ A, int lda, int a_hi, int K,
    const __half* __restrict__ Wp,
    const float* __restrict__ bias,
    __half* __restrict__ out, int ldo, int o_hi, int o_lo,
    const __half* __restrict__ aux, int ldx, int x_hi, int x_lo)
{
    extern __shared__ __align__(1024) char dsm[];
    const uint32_t sb = (uint32_t)__cvta_generic_to_shared(dsm);
    const int tid = threadIdx.x, lane = tid & 31, warp = tid >> 5;
    const int wm = warp >> 1, wn = warp & 1;
    const int bm = blockIdx.x, bn = blockIdx.y;
    const int KT = K >> 6;

    float acc[2][8][4];
    #pragma unroll
    for (int i = 0; i < 2; i++)
        #pragma unroll
        for (int j = 0; j < 8; j++)
            #pragma unroll
            for (int q = 0; q < 4; q++) acc[i][j][q] = 0.f;

    const __half* Ab = A  + (size_t)bm * 128 * lda;
    const __half* Bb = Wp + (size_t)bn * 128 * K;

    auto load_stage = [&](int s, int kt) {
        const int k0 = kt << 6;
        #pragma unroll
        for (int i = 0; i < 4; i++) {
            const int id = tid + 256 * i;
            const int row = id >> 3, c = id & 7;
            const uint32_t sw = (row << 7) | ((c ^ (row & 7)) << 4);
            cp16s(sb + SAH(s) + sw, Ab + (size_t)row * lda + a_hi + k0 + c * 8);
            cp16s(sb + SBB(s) + sw, Bb + (size_t)row * K   + k0   + c * 8);
        }
        asm volatile("cp.async.commit_group;");
    };

    load_stage(0, 0);
    load_stage(1, 1);

    const int lrow = lane & 15;
    const int lhi  = lane >> 4;
    const int lph  = lane & 7;
    const uint32_t aRow0 = (uint32_t)(wm * 32 + lrow) << 7;
    const uint32_t bRow0 = (uint32_t)(wn * 64 + lrow) << 7;

    int s = 0;
    for (int kt = 0; kt < KT; kt++) {
        if (kt + 2 < KT) {
            int s2 = s + 2; if (s2 >= 3) s2 -= 3;
            load_stage(s2, kt + 2);
            asm volatile("cp.async.wait_group 2;");
        } else if (kt + 1 < KT) {
            asm volatile("cp.async.wait_group 1;");
        } else {
            asm volatile("cp.async.wait_group 0;");
        }
        __syncthreads();
        const uint32_t aH = sb + SAH(s);
        const uint32_t bS = sb + SBB(s);

        #pragma unroll
        for (int kq = 0; kq < 4; kq++) {
            const uint32_t cb = (uint32_t)(((kq * 2 + lhi) ^ lph) << 4);
            uint32_t ah[2][4], b[4][4];
            #pragma unroll
            for (int mi = 0; mi < 2; mi++)
                ldmx4(aH + aRow0 + (uint32_t)(mi * 2048) + cb, ah[mi][0], ah[mi][1], ah[mi][2], ah[mi][3]);
            #pragma unroll
            for (int n2 = 0; n2 < 4; n2++)
                ldmx4(bS + bRow0 + (uint32_t)(n2 * 2048) + cb, b[n2][0], b[n2][1], b[n2][2], b[n2][3]);
            #pragma unroll
            for (int mi = 0; mi < 2; mi++)
                #pragma unroll
                for (int ni = 0; ni < 8; ni++)
                    MMA16(acc[mi][ni], ah[mi][0], ah[mi][1], ah[mi][2], ah[mi][3],
                          b[ni >> 1][ni & 1], b[ni >> 1][2 + (ni & 1)]);
        }
        __syncthreads();
        if (++s >= 3) s -= 3;
    }

    #pragma unroll
    for (int mi = 0; mi < 2; mi++) {
        #pragma unroll
        for (int ni = 0; ni < 8; ni++) {
            const int r0 = bm * 128 + wm * 32 + mi * 16 + (lane >> 2);
            const int c  = bn * 128 + wn * 64 + ni * 8 + (lane & 3) * 2;
            epi_store<MODE>(r0,     c, acc[mi][ni][0], acc[mi][ni][1], bias, out, ldo, o_hi, o_lo, aux, ldx, x_hi, x_lo);
            epi_store<MODE>(r0 + 8, c, acc[mi][ni][2], acc[mi][ni][3], bias, out, ldo, o_hi, o_lo, aux, ldx, x_hi, x_lo);
        }
    }
}

// ---------------- final tiny projections ----------------
__global__ void head2_kernel(
    const float* __restrict__ hsW2, const float* __restrict__ hsb2,
    const float* __restrict__ heW2, const float* __restrict__ heb2,
    const float* __restrict__ hfW2, const float* __restrict__ hfb2,
    const float* __restrict__ hwW2, const float* __restrict__ hwb2,
    float* __restrict__ out)
{
    int row  = blockIdx.x * 8 + (threadIdx.x >> 5);
    int lane = threadIdx.x & 31;
    const __half* h0 = g_HEADH + (size_t)row * 1024;
    const __half* h1 = g_HEADH + (size_t)(BATCH + row) * 1024;
    const __half* h2 = g_HEADH + (size_t)(2 * BATCH + row) * 1024;
    const __half* h3 = g_HEADH + (size_t)(3 * BATCH + row) * 1024;
    float acc[7] = {0.f, 0.f, 0.f, 0.f, 0.f, 0.f, 0.f};
    for (int k = lane; k < 512; k += 32) {
        float x0 = __half2float(h0[k]) + __half2float(h0[512 + k]);
        float x1 = __half2float(h1[k]) + __half2float(h1[512 + k]);
        float x2 = __half2float(h2[k]) + __half2float(h2[512 + k]);
        float x3 = __half2float(h3[k]) + __half2float(h3[512 + k]);
        acc[0] = fmaf(x0, hsW2[k * 3 + 0], acc[0]);
        acc[1] = fmaf(x0, hsW2[k * 3 + 1], acc[1]);
        acc[2] = fmaf(x0, hsW2[k * 3 + 2], acc[2]);
        acc[3] = fmaf(x1, heW2[k],         acc[3]);
        acc[4] = fmaf(x2, hfW2[k],         acc[4]);
        acc[5] = fmaf(x3, hwW2[k * 2 + 0], acc[5]);
        acc[6] = fmaf(x3, hwW2[k * 2 + 1], acc[6]);
    }
    #pragma unroll
    for (int j = 0; j < 7; j++)
        #pragma unroll
        for (int o = 16; o > 0; o >>= 1)
            acc[j] += __shfl_xor_sync(0xffffffffu, acc[j], o);
    if (lane == 0) {
        float* orow = out + (size_t)row * 7;
        orow[0] = acc[0] + hsb2[0];
        orow[1] = acc[1] + hsb2[1];
        orow[2] = acc[2] + hsb2[2];
        orow[3] = acc[3] + heb2[0];
        orow[4] = acc[4] + hfb2[0];
        orow[5] = acc[5] + hwb2[0];
        orow[6] = acc[6] + hwb2[1];
    }
}

// ---------------- host launch ----------------
extern "C" void kernel_launch(void* const* d_in, const int* in_sizes, int n_in,
                              void* d_out, int out_size) {
    (void)in_sizes; (void)n_in; (void)out_size;
    const float* sh    = (const float*)d_in[0];
    const float* el    = (const float*)d_in[1];
    const float* fa    = (const float*)d_in[2];
    const float* wr    = (const float*)d_in[3];
    const float* s2e_W = (const float*)d_in[4];
    const float* s2e_b = (const float*)d_in[5];
    const float* tf_W  = (const float*)d_in[6];
    const float* tf_b  = (const float*)d_in[7];
    const float* fw_W  = (const float*)d_in[8];
    const float* fw_b  = (const float*)d_in[9];
    const float* fg_W  = (const float*)d_in[10];
    const float* fg_b  = (const float*)d_in[11];
    const float* wg_W  = (const float*)d_in[12];
    const float* wg_b  = (const float*)d_in[13];
    const float* hsW1  = (const float*)d_in[14];
    const float* hsb1  = (const float*)d_in[15];
    const float* hsW2  = (const float*)d_in[16];
    const float* hsb2  = (const float*)d_in[17];
    const float* heW1  = (const float*)d_in[18];
    const float* heb1  = (const float*)d_in[19];
    const float* heW2  = (const float*)d_in[20];
    const float* heb2  = (const float*)d_in[21];
    const float* hfW1  = (const float*)d_in[22];
    const float* hfb1  = (const float*)d_in[23];
    const float* hfW2  = (const float*)d_in[24];
    const float* hfb2  = (const float*)d_in[25];
    const float* hwW1  = (const float*)d_in[26];
    const float* hwb1  = (const float*)d_in[27];
    const float* hwW2  = (const float*)d_in[28];
    const float* hwb2  = (const float*)d_in[29];

    __half *WP, *MEGA, *SCRATCH, *HEADH;
    cudaGetSymbolAddress((void**)&WP,      g_WP);
    cudaGetSymbolAddress((void**)&MEGA,    g_MEGA);
    cudaGetSymbolAddress((void**)&SCRATCH, g_SCRATCH);
    cudaGetSymbolAddress((void**)&HEADH,   g_HEADH);

    cudaFuncSetAttribute(gemm_lm<MODE_PLAIN>, cudaFuncAttributeMaxDynamicSharedMemorySize, GEMM_SMEM);
    cudaFuncSetAttribute(gemm_lm<MODE_ADD>,   cudaFuncAttributeMaxDynamicSharedMemorySize, GEMM_SMEM);
    cudaFuncSetAttribute(gemm_lm<MODE_GATE>,  cudaFuncAttributeMaxDynamicSharedMemorySize, GEMM_SMEM);
    cudaFuncSetAttribute(gemm_lm<MODE_GELU>,  cudaFuncAttributeMaxDynamicSharedMemorySize, GEMM_SMEM);

    split_inputs_kernel<<<(BATCH * HDIM + 255) / 256, 256>>>(sh, el, fa, wr);

    pack_tiled<<<dim3(16, 16, 5), 256>>>(s2e_W, WP + S2E_OFF, 512);
    pack_tiled<<<dim3(32, 16, 5), 256>>>(tf_W,  WP + TF_OFF,  1024);
    pack_tiled<<<dim3(16, 16, 5), 256>>>(fg_W,  WP + FG_OFF,  512);
    pack_tiled<<<dim3(32, 16, 5), 256>>>(fw_W,  WP + FW_OFF,  1024);
    pack_tiled<<<dim3(16, 16, 5), 256>>>(wg_W,  WP + WG_OFF,  512);
    pack_tiled<<<dim3(16, 16, 1), 256>>>(hsW1, WP + H1_OFF + 0 * S2E_SZ, 512);
    pack_tiled<<<dim3(16, 16, 1), 256>>>(heW1, WP + H1_OFF + 1 * S2E_SZ, 512);
    pack_tiled<<<dim3(16, 16, 1), 256>>>(hfW1, WP + H1_OFF + 2 * S2E_SZ, 512);
    pack_tiled<<<dim3(16, 16, 1), 256>>>(hwW1, WP + H1_OFF + 3 * S2E_SZ, 512);

    dim3 grid(BATCH / 128, 512 / 128);
    for (int i = 0; i < NL; i++) {
        // e = e + sh @ W + b   (A = sh_hi)
        gemm_lm<MODE_ADD><<<grid, 256, GEMM_SMEM>>>(
            MEGA, 4096, 0, 512,
            WP + S2E_OFF + (size_t)i * S2E_SZ, s2e_b + i * 512,
            MEGA, 4096, 512, 2560, nullptr, 0, 0, 0);
        // fm = [sh_hi, e_hi] @ W + b  (contiguous hi block at offset 0, K=1024)
        gemm_lm<MODE_PLAIN><<<grid, 256, GEMM_SMEM>>>(
            MEGA, 4096, 0, 1024,
            WP + TF_OFF + (size_t)i * TF_SZ, tf_b + i * 512,
            SCRATCH, 1024, 0, 512, nullptr, 0, 0, 0);
        // g = sigmoid(fm_hi @ W + b); f = f*(1-g) + fm*g
        gemm_lm<MODE_GATE><<<grid, 256, GEMM_SMEM>>>(
            SCRATCH, 1024, 0, 512,
            WP + FG_OFF + (size_t)i * S2E_SZ, fg_b + i * 512,
            MEGA, 4096, 1024, 3072, SCRATCH, 1024, 0, 512);
        // wm = [e_hi, f_hi] @ W + b  (contiguous hi block at offset 512, K=1024)
        gemm_lm<MODE_PLAIN><<<grid, 256, GEMM_SMEM>>>(
            MEGA, 4096, 512, 1024,
            WP + FW_OFF + (size_t)i * TF_SZ, fw_b + i * 512,
            SCRATCH, 1024, 0, 512, nullptr, 0, 0, 0);
        // g = sigmoid(wm_hi @ W + b); w = w*(1-g) + wm*g
        gemm_lm<MODE_GATE><<<grid, 256, GEMM_SMEM>>>(
            SCRATCH, 1024, 0, 512,
            WP + WG_OFF + (size_t)i * S2E_SZ, wg_b + i * 512,
            MEGA, 4096, 1536, 3584, SCRATCH, 1024, 0, 512);
    }

    const int xoff_hi[4] = {0, 512, 1024, 1536};
    const float* hb1[4]  = {hsb1, heb1, hfb1, hwb1};
    for (int j = 0; j < 4; j++) {
        gemm_lm<MODE_GELU><<<grid, 256, GEMM_SMEM>>>(
            MEGA, 4096, xoff_hi[j], 512,
            WP + H1_OFF + (size_t)j * S2E_SZ, hb1[j],
            HEADH + (size_t)j * BATCH * 1024, 1024, 0, 512, nullptr, 0, 0, 0);
    }

    head2_kernel<<<BATCH / 8, 256>>>(hsW2, hsb2, heW2, heb2, hfW2, hfb2,
                                     hwW2, hwb2, (float*)d_out);
}